// round 5
// baseline (speedup 1.0000x reference)
#include <cuda_runtime.h>
#include <cuda_fp16.h>
#include <cstdint>

#define NN 100000
#define H 128
#define NE 1600000
#define NL 3
#define OUTC 32
#define HMID 64

#define TILE_M 128
#define ALD 36

// ---------------- scratch ----------------
// 0=hu0 1=hu1 2=hi0 3=hi1 4=aggA(user, also cls-hid scratch) 5=aggB(item)
__device__ float g_big[(size_t)6 * NN * H];
__device__ __half g_hsh[2][(size_t)NN * H];   // fp16 shadow of current h_u / h_i (for gathers)
__device__ int g_rowptr[2][NN + 1];
__device__ int g_colv[2][NE];
__device__ int g_cnt[2][NN];
__device__ int g_cursor[2][NN];
__device__ int g_bsums[2][256];

__device__ __forceinline__ float* pick(int id) {
    return g_big + (size_t)id * NN * H;
}

__device__ __forceinline__ uint32_t to_tf32_u(float x) {
    uint32_t u;
    asm("cvt.rna.tf32.f32 %0, %1;" : "=r"(u) : "f"(x));
    return u;
}

__device__ __forceinline__ void mma_tf32(float c[4], const uint32_t a[4], const uint32_t b[2]) {
    asm volatile(
        "mma.sync.aligned.m16n8k8.row.col.f32.tf32.tf32.f32 "
        "{%0,%1,%2,%3}, {%4,%5,%6,%7}, {%8,%9}, {%0,%1,%2,%3};"
        : "+f"(c[0]), "+f"(c[1]), "+f"(c[2]), "+f"(c[3])
        : "r"(a[0]), "r"(a[1]), "r"(a[2]), "r"(a[3]), "r"(b[0]), "r"(b[1]));
}

__device__ __forceinline__ void cp16(uint32_t dst, const float* src) {
    asm volatile("cp.async.ca.shared.global [%0], [%1], 16;" :: "r"(dst), "l"(src));
}
__device__ __forceinline__ void cp_commit() { asm volatile("cp.async.commit_group;"); }

// ---------------- CSR build ----------------
__global__ void k_zero_cnt() {
    int i = blockIdx.x * blockDim.x + threadIdx.x;
    if (i < NN) { g_cnt[0][i] = 0; g_cnt[1][i] = 0; }
}

__global__ void k_hist2(const int* __restrict__ d0, const int* __restrict__ d1) {
    int et = blockIdx.y;
    const int* dst = et ? d1 : d0;
    int i = blockIdx.x * blockDim.x + threadIdx.x;
    if (i < NE) atomicAdd(&g_cnt[et][dst[i]], 1);
}

__global__ void k_scan1() {
    int et = blockIdx.y;
    __shared__ int s[1024];
    int i = blockIdx.x * 1024 + threadIdx.x;
    int v = (i < NN) ? g_cnt[et][i] : 0;
    s[threadIdx.x] = v;
    __syncthreads();
    for (int o = 1; o < 1024; o <<= 1) {
        int t = (threadIdx.x >= (unsigned)o) ? s[threadIdx.x - o] : 0;
        __syncthreads();
        s[threadIdx.x] += t;
        __syncthreads();
    }
    if (i < NN) g_rowptr[et][i + 1] = s[threadIdx.x];
    if (threadIdx.x == 1023) g_bsums[et][blockIdx.x] = s[1023];
    if (i == 0) g_rowptr[et][0] = 0;
}

__global__ void k_scan2p(int nb) {
    int et = blockIdx.y;
    __shared__ int s[128];
    int t = threadIdx.x;
    int v = (t < nb) ? g_bsums[et][t] : 0;
    s[t] = v;
    __syncthreads();
    for (int o = 1; o < 128; o <<= 1) {
        int u = (t >= o) ? s[t - o] : 0;
        __syncthreads();
        s[t] += u;
        __syncthreads();
    }
    if (t < nb) g_bsums[et][t] = s[t] - v;   // exclusive
}

__global__ void k_scan3() {
    int et = blockIdx.y;
    int i = blockIdx.x * 1024 + threadIdx.x;
    if (i < NN) {
        int v = g_rowptr[et][i + 1] + g_bsums[et][blockIdx.x];
        g_rowptr[et][i + 1] = v;
        g_cursor[et][i + 1] = v;
    }
    if (i == 0) g_cursor[et][0] = 0;
}

__global__ void k_fill2(const int* __restrict__ s0, const int* __restrict__ d0,
                        const int* __restrict__ s1, const int* __restrict__ d1) {
    int et = blockIdx.y;
    const int* src = et ? s1 : s0;
    const int* dst = et ? d1 : d0;
    int i = blockIdx.x * blockDim.x + threadIdx.x;
    if (i < NE) {
        int d = dst[i];
        int pz = atomicAdd(&g_cursor[et][d], 1);
        g_colv[et][pz] = src[i];
    }
}

// ---------------- mean aggregation from fp16 shadow (one warp per dst node) ----------------
struct H4 { __half2 a, b; };   // 8 bytes = 4 halves

__global__ void __launch_bounds__(256) k_agg2() {
    int et = blockIdx.y;    // 0: aggregate h_u (shadow 0) -> buf4 ; 1: h_i (shadow 1) -> buf5
    const H4* __restrict__ hv = (const H4*)g_hsh[et];
    float* __restrict__ outp = pick(et == 0 ? 4 : 5);
    int gw = (blockIdx.x * 256 + threadIdx.x) >> 5;
    int lane = threadIdx.x & 31;
    if (gw >= NN) return;
    int beg = g_rowptr[et][gw], end = g_rowptr[et][gw + 1];
    float ax = 0.f, ay = 0.f, az = 0.f, aw = 0.f;
    int e = beg;
    for (; e + 4 <= end; e += 4) {
        int s0 = g_colv[et][e], s1 = g_colv[et][e + 1];
        int s2 = g_colv[et][e + 2], s3 = g_colv[et][e + 3];
        H4 v0 = hv[s0 * 32 + lane];
        H4 v1 = hv[s1 * 32 + lane];
        H4 v2 = hv[s2 * 32 + lane];
        H4 v3 = hv[s3 * 32 + lane];
        float2 f0a = __half22float2(v0.a), f0b = __half22float2(v0.b);
        float2 f1a = __half22float2(v1.a), f1b = __half22float2(v1.b);
        float2 f2a = __half22float2(v2.a), f2b = __half22float2(v2.b);
        float2 f3a = __half22float2(v3.a), f3b = __half22float2(v3.b);
        ax += (f0a.x + f1a.x) + (f2a.x + f3a.x);
        ay += (f0a.y + f1a.y) + (f2a.y + f3a.y);
        az += (f0b.x + f1b.x) + (f2b.x + f3b.x);
        aw += (f0b.y + f1b.y) + (f2b.y + f3b.y);
    }
    for (; e < end; e++) {
        int s0 = g_colv[et][e];
        H4 v = hv[s0 * 32 + lane];
        float2 fa = __half22float2(v.a), fb = __half22float2(v.b);
        ax += fa.x; ay += fa.y; az += fb.x; aw += fb.y;
    }
    float invc = 1.0f / fmaxf((float)(end - beg), 1.0f);
    ((float4*)outp)[gw * 32 + lane] = make_float4(ax * invc, ay * invc, az * invc, aw * invc);
}

// ---------------- GEMM param set ----------------
struct GP {
    const float* A1p;   // external A (encoders); else pick(a1)
    const float* W1; const float* W2;
    const float* bias;
    const float* bng; const float* bnb; const float* bnm; const float* bnv;
    int a1, a2, res, out, sh;   // sh: fp16 shadow index to write (-1 none)
};

// ---------------- tensor-core GEMM, cp.async double-buffered ----------------
// MODE 0: out = relu(A1@W1 + bias)                      (K=128, N=NW)
// MODE 2: m = rownorm(A1@W1 + A2@W2 + bias); out = relu(bn(m + res))   (K=256 virt, N=128)
template <int MODE, int NT>
__global__ void __launch_bounds__(256, 2) k_gemm2(GP pa, GP pb) {
    constexpr int NST = (MODE == 0) ? 4 : 8;
    constexpr int NW = NT * 16;
    constexpr int WLD2 = NW + 8;
    constexpr int CPR = NW / 4;
    constexpr int WCH = (32 * CPR) / 256;
    constexpr int RJ = 256 / CPR;

    extern __shared__ float sm[];
    float* Ws = sm;                          // [2][32][WLD2]
    float* As = Ws + 2 * 32 * WLD2;          // [2][128][ALD]
    float* red = As + 2 * 128 * ALD;         // [128][2]

    GP P = (blockIdx.y == 0) ? pa : pb;
    const float* A1 = (P.a1 >= 0) ? pick(P.a1) : P.A1p;
    const float* A2 = (MODE == 2) ? pick(P.a2) : nullptr;
    const float* res = (MODE == 2) ? pick(P.res) : nullptr;
    float* out = pick(P.out);
    __half* hsh = (P.sh >= 0) ? g_hsh[P.sh] : nullptr;

    int tid = threadIdx.x;
    int lane = tid & 31, w = tid >> 5;
    int wm = w & 3, wn = w >> 2;
    int p = lane >> 2, q = lane & 3;

    uint32_t ws_u = (uint32_t)__cvta_generic_to_shared(Ws);
    uint32_t as_u = (uint32_t)__cvta_generic_to_shared(As);

    int rowbase = blockIdx.x * TILE_M;
    int arow = tid >> 3;
    int ac4 = (tid & 7) << 2;
    int garow[4];
#pragma unroll
    for (int j = 0; j < 4; j++) {
        int r = rowbase + arow + 32 * j;
        garow[j] = (r < NN) ? r : (NN - 1);
    }
    int wrow0 = tid / CPR;
    int wc4 = (tid % CPR) * 4;

    auto stage = [&](int buf, int s) {
        const float* Asrc = (MODE == 2 && s >= 4) ? A2 : A1;
        int ks = (s & 3) * 32;
#pragma unroll
        for (int j = 0; j < 4; j++) {
            uint32_t d = as_u + (uint32_t)((buf * 128 + arow + 32 * j) * ALD + ac4) * 4u;
            cp16(d, Asrc + (size_t)garow[j] * H + ks + ac4);
        }
#pragma unroll
        for (int j = 0; j < WCH; j++) {
            int row = wrow0 + RJ * j;
            int kw = s * 32 + row;
            const float* wsrc = (MODE == 2 && kw >= 128)
                                    ? (P.W2 + (size_t)(kw - 128) * NW + wc4)
                                    : (P.W1 + (size_t)kw * NW + wc4);
            uint32_t d = ws_u + (uint32_t)((buf * 32 + row) * WLD2 + wc4) * 4u;
            cp16(d, wsrc);
        }
    };

    float acc[2][NT][4];
#pragma unroll
    for (int mt = 0; mt < 2; mt++)
#pragma unroll
        for (int nt = 0; nt < NT; nt++)
#pragma unroll
            for (int e = 0; e < 4; e++) acc[mt][nt][e] = 0.f;

    stage(0, 0);
    cp_commit();

#pragma unroll 1
    for (int s = 0; s < NST; s++) {
        if (s + 1 < NST) {
            stage((s + 1) & 1, s + 1);
            cp_commit();
            asm volatile("cp.async.wait_group 1;");
        } else {
            asm volatile("cp.async.wait_group 0;");
        }
        __syncthreads();
        const float* Asb = As + (s & 1) * 128 * ALD;
        const float* Wsb = Ws + (s & 1) * 32 * WLD2;
#pragma unroll
        for (int cc = 0; cc < 4; cc++) {
            int kl = cc * 8;
            uint32_t a[2][4];
#pragma unroll
            for (int mt = 0; mt < 2; mt++) {
                int r = wm * 32 + mt * 16 + p;
                a[mt][0] = to_tf32_u(Asb[r * ALD + kl + q]);
                a[mt][1] = to_tf32_u(Asb[(r + 8) * ALD + kl + q]);
                a[mt][2] = to_tf32_u(Asb[r * ALD + kl + q + 4]);
                a[mt][3] = to_tf32_u(Asb[(r + 8) * ALD + kl + q + 4]);
            }
            uint32_t b[NT][2];
#pragma unroll
            for (int nt = 0; nt < NT; nt++) {
                int c = wn * (NT * 8) + nt * 8 + p;
                b[nt][0] = to_tf32_u(Wsb[(kl + q) * WLD2 + c]);
                b[nt][1] = to_tf32_u(Wsb[(kl + q + 4) * WLD2 + c]);
            }
#pragma unroll
            for (int mt = 0; mt < 2; mt++)
#pragma unroll
                for (int nt = 0; nt < NT; nt++)
                    mma_tf32(acc[mt][nt], a[mt], b[nt]);
        }
        __syncthreads();
    }

    // ---------------- epilogue ----------------
    float bv[NT][2];
#pragma unroll
    for (int nt = 0; nt < NT; nt++) {
        int c = wn * (NT * 8) + nt * 8 + 2 * q;
        bv[nt][0] = __ldg(&P.bias[c]);
        bv[nt][1] = __ldg(&P.bias[c + 1]);
    }
#pragma unroll
    for (int mt = 0; mt < 2; mt++)
#pragma unroll
        for (int nt = 0; nt < NT; nt++) {
            acc[mt][nt][0] += bv[nt][0];
            acc[mt][nt][1] += bv[nt][1];
            acc[mt][nt][2] += bv[nt][0];
            acc[mt][nt][3] += bv[nt][1];
        }

    if (MODE == 0) {
#pragma unroll
        for (int mt = 0; mt < 2; mt++)
#pragma unroll
            for (int rs = 0; rs < 2; rs++) {
                int r = rowbase + wm * 32 + mt * 16 + p + rs * 8;
                if (r < NN) {
#pragma unroll
                    for (int nt = 0; nt < NT; nt++) {
                        int c = wn * (NT * 8) + nt * 8 + 2 * q;
                        float2 o = make_float2(fmaxf(acc[mt][nt][rs * 2], 0.f),
                                               fmaxf(acc[mt][nt][rs * 2 + 1], 0.f));
                        *(float2*)&out[(size_t)r * NW + c] = o;
                        if (hsh)
                            *(__half2*)&hsh[(size_t)r * H + c] = __floats2half2_rn(o.x, o.y);
                    }
                }
            }
    } else {
        float ss[2][2];
#pragma unroll
        for (int mt = 0; mt < 2; mt++) {
            ss[mt][0] = 0.f; ss[mt][1] = 0.f;
#pragma unroll
            for (int nt = 0; nt < NT; nt++) {
                ss[mt][0] = fmaf(acc[mt][nt][0], acc[mt][nt][0],
                            fmaf(acc[mt][nt][1], acc[mt][nt][1], ss[mt][0]));
                ss[mt][1] = fmaf(acc[mt][nt][2], acc[mt][nt][2],
                            fmaf(acc[mt][nt][3], acc[mt][nt][3], ss[mt][1]));
            }
#pragma unroll
            for (int rs = 0; rs < 2; rs++) {
                ss[mt][rs] += __shfl_xor_sync(0xffffffffu, ss[mt][rs], 1);
                ss[mt][rs] += __shfl_xor_sync(0xffffffffu, ss[mt][rs], 2);
            }
        }
        if (q == 0) {
#pragma unroll
            for (int mt = 0; mt < 2; mt++) {
                red[(wm * 32 + mt * 16 + p) * 2 + wn]     = ss[mt][0];
                red[(wm * 32 + mt * 16 + p + 8) * 2 + wn] = ss[mt][1];
            }
        }
        __syncthreads();

        float scl[NT][2], mh[NT][2], bb[NT][2];
#pragma unroll
        for (int nt = 0; nt < NT; nt++) {
            int c = wn * (NT * 8) + nt * 8 + 2 * q;
            scl[nt][0] = __ldg(&P.bng[c])     * rsqrtf(__ldg(&P.bnv[c]) + 1e-5f);
            scl[nt][1] = __ldg(&P.bng[c + 1]) * rsqrtf(__ldg(&P.bnv[c + 1]) + 1e-5f);
            mh[nt][0] = __ldg(&P.bnm[c]);     mh[nt][1] = __ldg(&P.bnm[c + 1]);
            bb[nt][0] = __ldg(&P.bnb[c]);     bb[nt][1] = __ldg(&P.bnb[c + 1]);
        }
#pragma unroll
        for (int mt = 0; mt < 2; mt++)
#pragma unroll
            for (int rs = 0; rs < 2; rs++) {
                int lr = wm * 32 + mt * 16 + p + rs * 8;
                float tot = red[lr * 2] + red[lr * 2 + 1];
                float inv = 1.0f / fmaxf(sqrtf(tot), 1e-12f);
                int r = rowbase + lr;
                if (r < NN) {
#pragma unroll
                    for (int nt = 0; nt < NT; nt++) {
                        int c = wn * (NT * 8) + nt * 8 + 2 * q;
                        float2 h = *(const float2*)&res[(size_t)r * H + c];
                        float t0 = fmaf(acc[mt][nt][rs * 2], inv, h.x);
                        float t1 = fmaf(acc[mt][nt][rs * 2 + 1], inv, h.y);
                        float2 o = make_float2(
                            fmaxf(fmaf(t0 - mh[nt][0], scl[nt][0], bb[nt][0]), 0.f),
                            fmaxf(fmaf(t1 - mh[nt][1], scl[nt][1], bb[nt][1]), 0.f));
                        *(float2*)&out[(size_t)r * H + c] = o;
                        if (hsh)
                            *(__half2*)&hsh[(size_t)r * H + c] = __floats2half2_rn(o.x, o.y);
                    }
                }
            }
    }
}

// ---------------- classifier stage 2: out = hid@W2 + b2 ----------------
__global__ void __launch_bounds__(256) k_cls2(const float* __restrict__ W2,
                                              const float* __restrict__ b2,
                                              float* __restrict__ out) {
    __shared__ float W2s[HMID * OUTC];
    __shared__ float b2s[OUTC];
    int tid = threadIdx.x;
#pragma unroll
    for (int j = 0; j < 8; j++) W2s[tid + 256 * j] = W2[tid + 256 * j];
    if (tid < OUTC) b2s[tid] = b2[tid];
    __syncthreads();

    int r = blockIdx.x * 256 + tid;
    if (r >= NN) return;
    const float* hid = pick(4) + (size_t)r * HMID;

    float acc[OUTC];
#pragma unroll
    for (int c = 0; c < OUTC; c++) acc[c] = b2s[c];
#pragma unroll
    for (int k4 = 0; k4 < HMID / 4; k4++) {
        float4 a = *(const float4*)(hid + k4 * 4);
        float av[4] = {a.x, a.y, a.z, a.w};
#pragma unroll
        for (int kk = 0; kk < 4; kk++) {
            const float* wr = &W2s[(k4 * 4 + kk) * OUTC];
#pragma unroll
            for (int c = 0; c < OUTC; c++) acc[c] = fmaf(av[kk], wr[c], acc[c]);
        }
    }
#pragma unroll
    for (int c4 = 0; c4 < OUTC / 4; c4++)
        *(float4*)&out[(size_t)r * OUTC + c4 * 4] =
            make_float4(acc[c4 * 4], acc[c4 * 4 + 1], acc[c4 * 4 + 2], acc[c4 * 4 + 3]);
}

// ---------------- launch ----------------
extern "C" void kernel_launch(void* const* d_in, const int* in_sizes, int n_in,
                              void* d_out, int out_size) {
    const float* x_user  = (const float*)d_in[0];
    const float* x_item  = (const float*)d_in[1];
    const float* enc_W_u = (const float*)d_in[2];
    const float* enc_b_u = (const float*)d_in[3];
    const float* enc_W_i = (const float*)d_in[4];
    const float* enc_b_i = (const float*)d_in[5];
    const float* Wl_ui = (const float*)d_in[6];
    const float* bl_ui = (const float*)d_in[7];
    const float* Wr_ui = (const float*)d_in[8];
    const float* Wl_iu = (const float*)d_in[9];
    const float* bl_iu = (const float*)d_in[10];
    const float* Wr_iu = (const float*)d_in[11];
    const float* bng_u = (const float*)d_in[12];
    const float* bnb_u = (const float*)d_in[13];
    const float* bnm_u = (const float*)d_in[14];
    const float* bnv_u = (const float*)d_in[15];
    const float* bng_i = (const float*)d_in[16];
    const float* bnb_i = (const float*)d_in[17];
    const float* bnm_i = (const float*)d_in[18];
    const float* bnv_i = (const float*)d_in[19];
    const float* cW1 = (const float*)d_in[20];
    const float* cb1 = (const float*)d_in[21];
    const float* cW2 = (const float*)d_in[22];
    const float* cb2 = (const float*)d_in[23];
    const int* ei_ui = (const int*)d_in[24];
    const int* ei_iu = (const int*)d_in[25];
    float* outp = (float*)d_out;

    const int SMEM_N8 = (2 * 32 * 136 + 2 * 128 * ALD + 256) * 4;  // 72,704
    const int SMEM_N4 = (2 * 32 * 72  + 2 * 128 * ALD + 256) * 4;  // 56,320

    cudaFuncSetAttribute(k_gemm2<0, 8>, cudaFuncAttributeMaxDynamicSharedMemorySize, SMEM_N8);
    cudaFuncSetAttribute(k_gemm2<2, 8>, cudaFuncAttributeMaxDynamicSharedMemorySize, SMEM_N8);
    cudaFuncSetAttribute(k_gemm2<0, 4>, cudaFuncAttributeMaxDynamicSharedMemorySize, SMEM_N4);

    const int GEMM_GRID = (NN + TILE_M - 1) / TILE_M;   // 782
    const int EB = (NE + 255) / 256;
    const int NB = (NN + 255) / 256;
    const int SB = (NN + 1023) / 1024;

    // ---- CSR (both edge types via blockIdx.y) ----
    k_zero_cnt<<<NB, 256>>>();
    k_hist2<<<dim3(EB, 2), 256>>>(ei_ui + NE, ei_iu + NE);
    k_scan1<<<dim3(SB, 2), 1024>>>();
    k_scan2p<<<dim3(1, 2), 128>>>(SB);
    k_scan3<<<dim3(SB, 2), 1024>>>();
    k_fill2<<<dim3(EB, 2), 256>>>(ei_ui, ei_ui + NE, ei_iu, ei_iu + NE);

    GP z{};
    z.a1 = z.a2 = z.res = z.out = 0;
    z.sh = -1;

    // ---- encoders (merged): h_u -> buf0 (+shadow0), h_i -> buf2 (+shadow1) ----
    {
        GP pa = z, pb = z;
        pa.A1p = x_user; pa.W1 = enc_W_u; pa.bias = enc_b_u; pa.a1 = -1; pa.out = 0; pa.sh = 0;
        pb.A1p = x_item; pb.W1 = enc_W_i; pb.bias = enc_b_i; pb.a1 = -1; pb.out = 2; pb.sh = 1;
        k_gemm2<0, 8><<<dim3(GEMM_GRID, 2), 256, SMEM_N8>>>(pa, pb);
    }

    for (int l = 0; l < NL; l++) {
        int hu_cur = l & 1, hu_next = (l + 1) & 1;
        int hi_cur = 2 + (l & 1), hi_next = 2 + ((l + 1) & 1);

        // aggA = mean_ui(shadow h_u) -> buf4 ; aggB = mean_iu(shadow h_i) -> buf5
        k_agg2<<<dim3(NN / 8, 2), 256>>>();

        GP pa = z, pb = z;
        // user update: m_user = rownorm(aggB@Wl_iu + h_i@Wr_iu + b); hu_next = relu(bn_u(m_user + hu_cur))
        pa.a1 = 5; pa.a2 = hi_cur; pa.res = hu_cur; pa.out = hu_next; pa.sh = 0;
        pa.W1 = Wl_iu + (size_t)l * H * H; pa.W2 = Wr_iu + (size_t)l * H * H;
        pa.bias = bl_iu + (size_t)l * H;
        pa.bng = bng_u + (size_t)l * H; pa.bnb = bnb_u + (size_t)l * H;
        pa.bnm = bnm_u + (size_t)l * H; pa.bnv = bnv_u + (size_t)l * H;
        // item update: m_item = rownorm(aggA@Wl_ui + h_u@Wr_ui + b); hi_next = relu(bn_i(m_item + hi_cur))
        pb.a1 = 4; pb.a2 = hu_cur; pb.res = hi_cur; pb.out = hi_next; pb.sh = 1;
        pb.W1 = Wl_ui + (size_t)l * H * H; pb.W2 = Wr_ui + (size_t)l * H * H;
        pb.bias = bl_ui + (size_t)l * H;
        pb.bng = bng_i + (size_t)l * H; pb.bnb = bnb_i + (size_t)l * H;
        pb.bnm = bnm_i + (size_t)l * H; pb.bnv = bnv_i + (size_t)l * H;

        k_gemm2<2, 8><<<dim3(GEMM_GRID, 2), 256, SMEM_N8>>>(pa, pb);
    }

    // ---- classifier: hid = relu(h_u@W1 + b1) -> buf4 (stride 64); out = hid@W2 + b2 ----
    {
        GP pc = z;
        pc.a1 = (NL & 1);           // final h_u buffer
        pc.W1 = cW1; pc.bias = cb1; pc.out = 4; pc.sh = -1;
        k_gemm2<0, 4><<<dim3(GEMM_GRID, 1), 256, SMEM_N4>>>(pc, pc);
        k_cls2<<<NB, 256>>>(cW2, cb2, outp);
    }
}